// round 15
// baseline (speedup 1.0000x reference)
#include <cuda_runtime.h>
#include <cuda_fp16.h>

// Shifted-window attention (UniMatch/Swin), B=8, H=96, W=128, C=128, NS=4.
// prep: k/v -> fp16 rolled+split order. attention: BM=256 (M=32/warp), fp16
// mma.m16n8k16 with F16 ACCUMULATORS for QK (Q pre-scaled by 1/sqrt(128) so
// partial sums stay O(1)), f32 acc for PV, cp.async double-buffered K/V,
// fused softmax+PV, mask-aware block skipping.

namespace {
constexpr int H_IMG = 96, W_IMG = 128, C_DIM = 128;
constexpr int WSH = 24, WSW = 32, SHF = 12, SWF = 16;
constexpr int NWIN = 128, NTOK = 768;
constexpr int BM = 256, BN = 64;
constexpr int NKT = 12, NQT = 3;
constexpr int STRB = 272;                   // smem row stride bytes (136 halfs; ≡16 mod 128)
constexpr int SM_Q  = 0;                    // 256 rows
constexpr int SM_K0 = SM_Q  + BM * STRB;    // 69632
constexpr int SM_V0 = SM_K0 + BN * STRB;    // 87040
constexpr int SM_K1 = SM_V0 + BN * STRB;    // 104448
constexpr int SM_V1 = SM_K1 + BN * STRB;    // 121856
constexpr int SMEM_BYTES = SM_V1 + BN * STRB;   // 139264 -> 1 CTA/SM
constexpr float QSCALE = 0.088388347648318447f; // 1/sqrt(128), folded into Q
constexpr float LOG2E  = 1.44269504089f;        // S is pre-scaled; exponent = S*log2e
constexpr float MASKB  = -144.26950409f;        // -100*log2(e)
}

__device__ __half g_k16[NWIN * NTOK * C_DIM];
__device__ __half g_v16[NWIN * NTOK * C_DIM];

// token index within window -> global token row (roll(-12,-16) + split; self-inverse)
__device__ __forceinline__ int grow_idx(int b, int wy, int wx, int t) {
    int r = t >> 5, cc = t & 31;
    int hi = wy * WSH + r + SHF; if (hi >= H_IMG) hi -= H_IMG;
    int wi = wx * WSW + cc + SWF; if (wi >= W_IMG) wi -= W_IMG;
    return b * (H_IMG * W_IMG) + hi * W_IMG + wi;
}

__device__ __forceinline__ unsigned h2u(__half2 h) { return *reinterpret_cast<unsigned*>(&h); }
__device__ __forceinline__ float ex2f(float x) {
    float r; asm("ex2.approx.f32 %0, %1;" : "=f"(r) : "f"(x)); return r;
}

// ---------------- pass 1: convert + reorder K/V ----------------
__global__ __launch_bounds__(256)
void prep_f16(const float* __restrict__ k, const float* __restrict__ v) {
    const int lane = threadIdx.x & 31, warp = threadIdx.x >> 5;
    const int win = blockIdx.y, b = win >> 4, widx = win & 15;
    const int wy = widx >> 2, wx = widx & 3;
    const int tbase = blockIdx.x * 64;
    #pragma unroll
    for (int s = 0; s < 8; ++s) {
        int t = tbase + warp * 8 + s;
        int row = grow_idx(b, wy, wx, t);
        size_t src = (size_t)row * C_DIM;
        size_t dst = ((size_t)win * NTOK + t) * C_DIM + lane * 4;
        float4 c = reinterpret_cast<const float4*>(k + src)[lane];
        *reinterpret_cast<uint2*>(g_k16 + dst) =
            make_uint2(h2u(__floats2half2_rn(c.x, c.y)), h2u(__floats2half2_rn(c.z, c.w)));
        float4 d = reinterpret_cast<const float4*>(v + src)[lane];
        *reinterpret_cast<uint2*>(g_v16 + dst) =
            make_uint2(h2u(__floats2half2_rn(d.x, d.y)), h2u(__floats2half2_rn(d.z, d.w)));
    }
}

// ---------------- pass 2: attention ----------------
__device__ __forceinline__ void mma_f16(float& c0, float& c1, float& c2, float& c3,
                                        unsigned a0, unsigned a1, unsigned a2, unsigned a3,
                                        unsigned b0, unsigned b1) {
    asm volatile(
        "mma.sync.aligned.m16n8k16.row.col.f32.f16.f16.f32 "
        "{%0,%1,%2,%3}, {%4,%5,%6,%7}, {%8,%9}, {%0,%1,%2,%3};"
        : "+f"(c0), "+f"(c1), "+f"(c2), "+f"(c3)
        : "r"(a0), "r"(a1), "r"(a2), "r"(a3), "r"(b0), "r"(b1));
}
// f16-accumulator variant: 2 packed f16x2 outputs (row lr / row lr+8)
__device__ __forceinline__ void mma_f16acc(unsigned& c0, unsigned& c1,
                                           unsigned a0, unsigned a1, unsigned a2, unsigned a3,
                                           unsigned b0, unsigned b1) {
    asm volatile(
        "mma.sync.aligned.m16n8k16.row.col.f16.f16.f16.f16 "
        "{%0,%1}, {%2,%3,%4,%5}, {%6,%7}, {%0,%1};"
        : "+r"(c0), "+r"(c1)
        : "r"(a0), "r"(a1), "r"(a2), "r"(a3), "r"(b0), "r"(b1));
}
#define LDSM_X4(r0, r1, r2, r3, addr)                                            \
    asm volatile("ldmatrix.sync.aligned.m8n8.x4.shared.b16 {%0,%1,%2,%3}, [%4];" \
                 : "=r"(r0), "=r"(r1), "=r"(r2), "=r"(r3) : "r"(addr))
#define LDSM_X4_T(r0, r1, r2, r3, addr)                                                \
    asm volatile("ldmatrix.sync.aligned.m8n8.x4.trans.shared.b16 {%0,%1,%2,%3}, [%4];" \
                 : "=r"(r0), "=r"(r1), "=r"(r2), "=r"(r3) : "r"(addr))
#define CP16(dst, src) \
    asm volatile("cp.async.cg.shared.global [%0], [%1], 16;" :: "r"(dst), "l"(src))
#define CP_COMMIT() asm volatile("cp.async.commit_group;" ::: "memory")
#define CP_WAIT(n)  asm volatile("cp.async.wait_group %0;" :: "n"(n) : "memory")

__global__ __launch_bounds__(256, 1)
void swin_attn_f16(const float* __restrict__ q, float* __restrict__ out) {
    extern __shared__ char smem[];
    const unsigned sb = (unsigned)__cvta_generic_to_shared(smem);

    const int tid  = threadIdx.x;
    const int lane = tid & 31;
    const int warp = tid >> 5;          // 0..7, owns q-rows 32*warp..+31 (2 A-tiles)
    const int lr   = lane >> 2;
    const int lc   = lane & 3;

    const int win  = blockIdx.y;
    const int b    = win >> 4;
    const int widx = win & 15;
    const int wy   = widx >> 2;
    const int wx   = widx & 3;
    const int qbase = blockIdx.x * BM;
    const bool wy3 = (wy == 3);
    const bool wx3 = (wx == 3);

    const __half* ksrc = g_k16 + (size_t)win * NTOK * C_DIM;
    const __half* vsrc = g_v16 + (size_t)win * NTOK * C_DIM;

    // ---- prologue: KV tile 0 via cp.async, then Q f32 -> f16 (pre-scaled) ----
    #pragma unroll
    for (int i = 0; i < 4; ++i) {
        int ch = i * 256 + tid, row = ch >> 4, c16 = ch & 15;
        CP16(sb + SM_K0 + row * STRB + c16 * 16, ksrc + row * C_DIM + c16 * 8);
        CP16(sb + SM_V0 + row * STRB + c16 * 16, vsrc + row * C_DIM + c16 * 8);
    }
    CP_COMMIT();

    #pragma unroll
    for (int s = 0; s < 32; ++s) {
        int local = warp * 32 + s;
        int row = grow_idx(b, wy, wx, qbase + local);
        float4 val = reinterpret_cast<const float4*>(q + (size_t)row * C_DIM)[lane];
        *reinterpret_cast<uint2*>(smem + SM_Q + local * STRB + lane * 8) =
            make_uint2(h2u(__floats2half2_rn(val.x * QSCALE, val.y * QSCALE)),
                       h2u(__floats2half2_rn(val.z * QSCALE, val.w * QSCALE)));
    }

    // q-region row id: one per warp (all 32 tokens share a window-row)
    const int qrh_all = wy3 ? ((((qbase + warp * 32) >> 5) < 12) ? 1 : 2) : 0;

    // ldmatrix lane-address offsets (bytes)
    const unsigned q_lds0 = sb + SM_Q + (warp * 32 + (lane & 15)) * STRB + (lane & 16);
    const unsigned q_lds1 = q_lds0 + 16 * STRB;
    const unsigned koff   = ((lane & 7) + ((lane & 16) >> 1)) * STRB + (lane & 8) * 2;
    const unsigned voff   = ((lane & 7) + (lane & 8)) * STRB + (lane & 16);

    float o[2][16][4];
    #pragma unroll
    for (int at = 0; at < 2; ++at)
        #pragma unroll
        for (int t = 0; t < 16; ++t)
            o[at][t][0] = o[at][t][1] = o[at][t][2] = o[at][t][3] = 0.f;
    float lsum[2][2] = {{0.f, 0.f}, {0.f, 0.f}};

    for (int kt = 0; kt < NKT; ++kt) {
        if (kt < NKT - 1) {
            const unsigned kb = sb + (((kt + 1) & 1) ? SM_K1 : SM_K0);
            const unsigned vb = sb + (((kt + 1) & 1) ? SM_V1 : SM_V0);
            const __half* ks = ksrc + (size_t)(kt + 1) * BN * C_DIM;
            const __half* vs = vsrc + (size_t)(kt + 1) * BN * C_DIM;
            #pragma unroll
            for (int i = 0; i < 4; ++i) {
                int ch = i * 256 + tid, row = ch >> 4, c16 = ch & 15;
                CP16(kb + row * STRB + c16 * 16, ks + row * C_DIM + c16 * 8);
                CP16(vb + row * STRB + c16 * 16, vs + row * C_DIM + c16 * 8);
            }
            CP_COMMIT();
            CP_WAIT(1);
        } else {
            CP_WAIT(0);
        }
        __syncthreads();

        // wy==3 row-region skip: all P of this kt are exactly 0 for mismatched warps
        const bool skip_kt = wy3 && (((kt < 6) ? 1 : 2) != qrh_all);
        if (!skip_kt) {
            const unsigned k_lds = sb + ((kt & 1) ? SM_K1 : SM_K0) + koff;
            const unsigned v_lds = sb + ((kt & 1) ? SM_V1 : SM_V0) + voff;

            // ---- S = Q K^T with f16 accumulators (S pre-scaled by 1/sqrt(128)).
            //      wx==3: at=0 needs even tp only, at=1 odd tp. ----
            unsigned acc[2][8][2];
            #pragma unroll
            for (int at = 0; at < 2; ++at)
                #pragma unroll
                for (int t = 0; t < 8; ++t) { acc[at][t][0] = 0u; acc[at][t][1] = 0u; }

            #pragma unroll
            for (int kk = 0; kk < 8; ++kk) {
                unsigned a00, a01, a02, a03, a10, a11, a12, a13;
                LDSM_X4(a00, a01, a02, a03, q_lds0 + kk * 32);
                LDSM_X4(a10, a11, a12, a13, q_lds1 + kk * 32);
                #pragma unroll
                for (int tp = 0; tp < 4; ++tp) {
                    unsigned b0, b1, b2, b3;
                    LDSM_X4(b0, b1, b2, b3, k_lds + tp * (16 * STRB) + kk * 32);
                    if (!wx3 || (tp & 1) == 0) {
                        mma_f16acc(acc[0][2*tp][0],   acc[0][2*tp][1],
                                   a00, a01, a02, a03, b0, b1);
                        mma_f16acc(acc[0][2*tp+1][0], acc[0][2*tp+1][1],
                                   a00, a01, a02, a03, b2, b3);
                    }
                    if (!wx3 || (tp & 1) == 1) {
                        mma_f16acc(acc[1][2*tp][0],   acc[1][2*tp][1],
                                   a10, a11, a12, a13, b0, b1);
                        mma_f16acc(acc[1][2*tp+1][0], acc[1][2*tp+1][1],
                                   a10, a11, a12, a13, b2, b3);
                    }
                }
            }

            // ---- FUSED softmax + PV per 16-token chunk s (tp==s).
            //      wx==3: chunk s feeds only at = s&1. ----
            const int krhA = wy3 ? (((2 * kt)     < 12) ? 1 : 2) : 0;
            const int krhB = wy3 ? (((2 * kt + 1) < 12) ? 1 : 2) : 0;
            #pragma unroll
            for (int s = 0; s < 4; ++s) {
                const bool a0on = !wx3 || ((s & 1) == 0);
                const bool a1on = !wx3 || ((s & 1) == 1);
                unsigned pas[2][4];
                #pragma unroll
                for (int at = 0; at < 2; ++at) {
                    if ((at == 0 && !a0on) || (at == 1 && !a1on)) continue;
                    #pragma unroll
                    for (int tt = 0; tt < 2; ++tt) {
                        const int t = 2 * s + tt;
                        const int krh = (t < 4) ? krhA : krhB;
                        const float bb = (krh == qrh_all) ? 0.f : MASKB;
                        float2 slo = __half22float2(
                            *reinterpret_cast<__half2*>(&acc[at][t][0]));
                        float2 shi = __half22float2(
                            *reinterpret_cast<__half2*>(&acc[at][t][1]));
                        float p0 = ex2f(fmaf(slo.x, LOG2E, bb));
                        float p1 = ex2f(fmaf(slo.y, LOG2E, bb));
                        float p2 = ex2f(fmaf(shi.x, LOG2E, bb));
                        float p3 = ex2f(fmaf(shi.y, LOG2E, bb));
                        lsum[at][0] += p0 + p1;
                        lsum[at][1] += p2 + p3;
                        pas[at][2 * tt]     = h2u(__floats2half2_rn(p0, p1));
                        pas[at][2 * tt + 1] = h2u(__floats2half2_rn(p2, p3));
                    }
                }
                #pragma unroll
                for (int cp = 0; cp < 8; ++cp) {
                    unsigned b0, b1, b2, b3;
                    LDSM_X4_T(b0, b1, b2, b3, v_lds + s * (16 * STRB) + cp * 32);
                    if (a0on) {
                        mma_f16(o[0][2*cp][0], o[0][2*cp][1], o[0][2*cp][2], o[0][2*cp][3],
                                pas[0][0], pas[0][1], pas[0][2], pas[0][3], b0, b1);
                        mma_f16(o[0][2*cp+1][0], o[0][2*cp+1][1], o[0][2*cp+1][2], o[0][2*cp+1][3],
                                pas[0][0], pas[0][1], pas[0][2], pas[0][3], b2, b3);
                    }
                    if (a1on) {
                        mma_f16(o[1][2*cp][0], o[1][2*cp][1], o[1][2*cp][2], o[1][2*cp][3],
                                pas[1][0], pas[1][1], pas[1][2], pas[1][3], b0, b1);
                        mma_f16(o[1][2*cp+1][0], o[1][2*cp+1][1], o[1][2*cp+1][2], o[1][2*cp+1][3],
                                pas[1][0], pas[1][1], pas[1][2], pas[1][3], b2, b3);
                    }
                }
            }
        }
        __syncthreads();
    }

    // ---- finish row sums + epilogue ----
    #pragma unroll
    for (int at = 0; at < 2; ++at) {
        float llo = lsum[at][0], lhi = lsum[at][1];
        llo += __shfl_xor_sync(0xffffffffu, llo, 1);
        llo += __shfl_xor_sync(0xffffffffu, llo, 2);
        lhi += __shfl_xor_sync(0xffffffffu, lhi, 1);
        lhi += __shfl_xor_sync(0xffffffffu, lhi, 2);
        const int tok_lo = qbase + warp * 32 + at * 16 + lr;
        const int gr_lo = grow_idx(b, wy, wx, tok_lo);
        const int gr_hi = grow_idx(b, wy, wx, tok_lo + 8);
        const float ilo = 1.f / llo;
        const float ihi = 1.f / lhi;
        float* out_lo = out + (size_t)gr_lo * C_DIM + 2 * lc;
        float* out_hi = out + (size_t)gr_hi * C_DIM + 2 * lc;
        #pragma unroll
        for (int t = 0; t < 16; ++t) {
            *reinterpret_cast<float2*>(&out_lo[8 * t]) =
                make_float2(o[at][t][0] * ilo, o[at][t][1] * ilo);
            *reinterpret_cast<float2*>(&out_hi[8 * t]) =
                make_float2(o[at][t][2] * ihi, o[at][t][3] * ihi);
        }
    }
}

extern "C" void kernel_launch(void* const* d_in, const int* in_sizes, int n_in,
                              void* d_out, int out_size) {
    (void)in_sizes; (void)n_in; (void)out_size;
    const float* q = (const float*)d_in[0];
    const float* k = (const float*)d_in[1];
    const float* v = (const float*)d_in[2];
    float* out = (float*)d_out;

    prep_f16<<<dim3(NKT, NWIN), 256>>>(k, v);

    cudaFuncSetAttribute(swin_attn_f16,
                         cudaFuncAttributeMaxDynamicSharedMemorySize, SMEM_BYTES);
    swin_attn_f16<<<dim3(NQT, NWIN), 256, SMEM_BYTES>>>(q, out);
}

// round 16
// speedup vs baseline: 1.0174x; 1.0174x over previous
#include <cuda_runtime.h>
#include <cuda_fp16.h>

// Shifted-window attention (UniMatch/Swin), B=8, H=96, W=128, C=128, NS=4.
// prep: k/v -> fp16 rolled+split order (wide 16B stores, bandwidth-optimal).
// attention (R14, best-known): BM=256 (M=32/warp), fp16 mma.m16n8k16 f32-acc,
// cp.async double-buffered K/V, fused softmax+PV, mask-aware block skipping.

namespace {
constexpr int H_IMG = 96, W_IMG = 128, C_DIM = 128;
constexpr int WSH = 24, WSW = 32, SHF = 12, SWF = 16;
constexpr int NWIN = 128, NTOK = 768;
constexpr int BM = 256, BN = 64;
constexpr int NKT = 12, NQT = 3;
constexpr int STRB = 272;                   // smem row stride bytes (136 halfs; ≡16 mod 128)
constexpr int SM_Q  = 0;                    // 256 rows
constexpr int SM_K0 = SM_Q  + BM * STRB;    // 69632
constexpr int SM_V0 = SM_K0 + BN * STRB;    // 87040
constexpr int SM_K1 = SM_V0 + BN * STRB;    // 104448
constexpr int SM_V1 = SM_K1 + BN * STRB;    // 121856
constexpr int SMEM_BYTES = SM_V1 + BN * STRB;   // 139264 -> 1 CTA/SM
constexpr float ISL2  = 0.12751744154f;     // log2(e)/sqrt(128)
constexpr float MASKB = -144.26950409f;     // -100*log2(e)
}

__device__ __half g_k16[NWIN * NTOK * C_DIM];
__device__ __half g_v16[NWIN * NTOK * C_DIM];

// token index within window -> global token row (roll(-12,-16) + split; self-inverse)
__device__ __forceinline__ int grow_idx(int b, int wy, int wx, int t) {
    int r = t >> 5, cc = t & 31;
    int hi = wy * WSH + r + SHF; if (hi >= H_IMG) hi -= H_IMG;
    int wi = wx * WSW + cc + SWF; if (wi >= W_IMG) wi -= W_IMG;
    return b * (H_IMG * W_IMG) + hi * W_IMG + wi;
}

__device__ __forceinline__ unsigned h2u(__half2 h) { return *reinterpret_cast<unsigned*>(&h); }
__device__ __forceinline__ float ex2f(float x) {
    float r; asm("ex2.approx.f32 %0, %1;" : "=f"(r) : "f"(x)); return r;
}

// ---------------- pass 1: convert + reorder K/V (wide stores) ----------------
// Each item = 8 consecutive channels of one token: 2x LDG.128 (f32) -> 1x STG.128 (f16x8).
__global__ __launch_bounds__(256)
void prep_f16(const float* __restrict__ k, const float* __restrict__ v) {
    const int win = blockIdx.y, b = win >> 4, widx = win & 15;
    const int wy = widx >> 2, wx = widx & 3;
    const int tbase = blockIdx.x * 64;

    #pragma unroll
    for (int i = 0; i < 4; ++i) {
        int idx = i * 256 + threadIdx.x;        // 1024 items per array per block
        int t   = tbase + (idx >> 4);           // token (64 per block)
        int c8  = idx & 15;                     // 8-channel chunk
        int row = grow_idx(b, wy, wx, t);
        const float4* ks = reinterpret_cast<const float4*>(k + (size_t)row * C_DIM + c8 * 8);
        const float4* vs = reinterpret_cast<const float4*>(v + (size_t)row * C_DIM + c8 * 8);
        size_t dst = ((size_t)win * NTOK + t) * C_DIM + c8 * 8;

        float4 ka = ks[0], kb = ks[1];
        *reinterpret_cast<uint4*>(g_k16 + dst) = make_uint4(
            h2u(__floats2half2_rn(ka.x, ka.y)), h2u(__floats2half2_rn(ka.z, ka.w)),
            h2u(__floats2half2_rn(kb.x, kb.y)), h2u(__floats2half2_rn(kb.z, kb.w)));
        float4 va = vs[0], vb = vs[1];
        *reinterpret_cast<uint4*>(g_v16 + dst) = make_uint4(
            h2u(__floats2half2_rn(va.x, va.y)), h2u(__floats2half2_rn(va.z, va.w)),
            h2u(__floats2half2_rn(vb.x, vb.y)), h2u(__floats2half2_rn(vb.z, vb.w)));
    }
}

// ---------------- pass 2: attention (R14 best-known, unchanged) ----------------
__device__ __forceinline__ void mma_f16(float& c0, float& c1, float& c2, float& c3,
                                        unsigned a0, unsigned a1, unsigned a2, unsigned a3,
                                        unsigned b0, unsigned b1) {
    asm volatile(
        "mma.sync.aligned.m16n8k16.row.col.f32.f16.f16.f32 "
        "{%0,%1,%2,%3}, {%4,%5,%6,%7}, {%8,%9}, {%0,%1,%2,%3};"
        : "+f"(c0), "+f"(c1), "+f"(c2), "+f"(c3)
        : "r"(a0), "r"(a1), "r"(a2), "r"(a3), "r"(b0), "r"(b1));
}
#define LDSM_X4(r0, r1, r2, r3, addr)                                            \
    asm volatile("ldmatrix.sync.aligned.m8n8.x4.shared.b16 {%0,%1,%2,%3}, [%4];" \
                 : "=r"(r0), "=r"(r1), "=r"(r2), "=r"(r3) : "r"(addr))
#define LDSM_X4_T(r0, r1, r2, r3, addr)                                                \
    asm volatile("ldmatrix.sync.aligned.m8n8.x4.trans.shared.b16 {%0,%1,%2,%3}, [%4];" \
                 : "=r"(r0), "=r"(r1), "=r"(r2), "=r"(r3) : "r"(addr))
#define CP16(dst, src) \
    asm volatile("cp.async.cg.shared.global [%0], [%1], 16;" :: "r"(dst), "l"(src))
#define CP_COMMIT() asm volatile("cp.async.commit_group;" ::: "memory")
#define CP_WAIT(n)  asm volatile("cp.async.wait_group %0;" :: "n"(n) : "memory")

__global__ __launch_bounds__(256, 1)
void swin_attn_f16(const float* __restrict__ q, float* __restrict__ out) {
    extern __shared__ char smem[];
    const unsigned sb = (unsigned)__cvta_generic_to_shared(smem);

    const int tid  = threadIdx.x;
    const int lane = tid & 31;
    const int warp = tid >> 5;          // 0..7, owns q-rows 32*warp..+31 (2 A-tiles)
    const int lr   = lane >> 2;
    const int lc   = lane & 3;

    const int win  = blockIdx.y;
    const int b    = win >> 4;
    const int widx = win & 15;
    const int wy   = widx >> 2;
    const int wx   = widx & 3;
    const int qbase = blockIdx.x * BM;
    const bool wy3 = (wy == 3);
    const bool wx3 = (wx == 3);

    const __half* ksrc = g_k16 + (size_t)win * NTOK * C_DIM;
    const __half* vsrc = g_v16 + (size_t)win * NTOK * C_DIM;

    // ---- prologue: KV tile 0 via cp.async, then Q f32 -> f16 ----
    #pragma unroll
    for (int i = 0; i < 4; ++i) {
        int ch = i * 256 + tid, row = ch >> 4, c16 = ch & 15;
        CP16(sb + SM_K0 + row * STRB + c16 * 16, ksrc + row * C_DIM + c16 * 8);
        CP16(sb + SM_V0 + row * STRB + c16 * 16, vsrc + row * C_DIM + c16 * 8);
    }
    CP_COMMIT();

    #pragma unroll
    for (int s = 0; s < 32; ++s) {
        int local = warp * 32 + s;
        int row = grow_idx(b, wy, wx, qbase + local);
        float4 val = reinterpret_cast<const float4*>(q + (size_t)row * C_DIM)[lane];
        *reinterpret_cast<uint2*>(smem + SM_Q + local * STRB + lane * 8) =
            make_uint2(h2u(__floats2half2_rn(val.x, val.y)),
                       h2u(__floats2half2_rn(val.z, val.w)));
    }

    // q-region row id: one per warp (all 32 tokens share a window-row)
    const int qrh_all = wy3 ? ((((qbase + warp * 32) >> 5) < 12) ? 1 : 2) : 0;

    // ldmatrix lane-address offsets (bytes)
    const unsigned q_lds0 = sb + SM_Q + (warp * 32 + (lane & 15)) * STRB + (lane & 16);
    const unsigned q_lds1 = q_lds0 + 16 * STRB;
    const unsigned koff   = ((lane & 7) + ((lane & 16) >> 1)) * STRB + (lane & 8) * 2;
    const unsigned voff   = ((lane & 7) + (lane & 8)) * STRB + (lane & 16);

    float o[2][16][4];
    #pragma unroll
    for (int at = 0; at < 2; ++at)
        #pragma unroll
        for (int t = 0; t < 16; ++t)
            o[at][t][0] = o[at][t][1] = o[at][t][2] = o[at][t][3] = 0.f;
    float lsum[2][2] = {{0.f, 0.f}, {0.f, 0.f}};

    for (int kt = 0; kt < NKT; ++kt) {
        if (kt < NKT - 1) {
            const unsigned kb = sb + (((kt + 1) & 1) ? SM_K1 : SM_K0);
            const unsigned vb = sb + (((kt + 1) & 1) ? SM_V1 : SM_V0);
            const __half* ks = ksrc + (size_t)(kt + 1) * BN * C_DIM;
            const __half* vs = vsrc + (size_t)(kt + 1) * BN * C_DIM;
            #pragma unroll
            for (int i = 0; i < 4; ++i) {
                int ch = i * 256 + tid, row = ch >> 4, c16 = ch & 15;
                CP16(kb + row * STRB + c16 * 16, ks + row * C_DIM + c16 * 8);
                CP16(vb + row * STRB + c16 * 16, vs + row * C_DIM + c16 * 8);
            }
            CP_COMMIT();
            CP_WAIT(1);
        } else {
            CP_WAIT(0);
        }
        __syncthreads();

        // wy==3 row-region skip: all P of this kt are exactly 0 for mismatched warps
        const bool skip_kt = wy3 && (((kt < 6) ? 1 : 2) != qrh_all);
        if (!skip_kt) {
            const unsigned k_lds = sb + ((kt & 1) ? SM_K1 : SM_K0) + koff;
            const unsigned v_lds = sb + ((kt & 1) ? SM_V1 : SM_V0) + voff;

            // ---- S = Q K^T. wx==3: at=0 only needs even tp (krw=1), at=1 odd tp. ----
            float acc[2][8][4];
            #pragma unroll
            for (int at = 0; at < 2; ++at)
                #pragma unroll
                for (int t = 0; t < 8; ++t)
                    acc[at][t][0] = acc[at][t][1] = acc[at][t][2] = acc[at][t][3] = 0.f;

            #pragma unroll
            for (int kk = 0; kk < 8; ++kk) {
                unsigned a00, a01, a02, a03, a10, a11, a12, a13;
                LDSM_X4(a00, a01, a02, a03, q_lds0 + kk * 32);
                LDSM_X4(a10, a11, a12, a13, q_lds1 + kk * 32);
                #pragma unroll
                for (int tp = 0; tp < 4; ++tp) {
                    unsigned b0, b1, b2, b3;
                    LDSM_X4(b0, b1, b2, b3, k_lds + tp * (16 * STRB) + kk * 32);
                    if (!wx3 || (tp & 1) == 0) {
                        mma_f16(acc[0][2*tp][0], acc[0][2*tp][1], acc[0][2*tp][2], acc[0][2*tp][3],
                                a00, a01, a02, a03, b0, b1);
                        mma_f16(acc[0][2*tp+1][0], acc[0][2*tp+1][1], acc[0][2*tp+1][2], acc[0][2*tp+1][3],
                                a00, a01, a02, a03, b2, b3);
                    }
                    if (!wx3 || (tp & 1) == 1) {
                        mma_f16(acc[1][2*tp][0], acc[1][2*tp][1], acc[1][2*tp][2], acc[1][2*tp][3],
                                a10, a11, a12, a13, b0, b1);
                        mma_f16(acc[1][2*tp+1][0], acc[1][2*tp+1][1], acc[1][2*tp+1][2], acc[1][2*tp+1][3],
                                a10, a11, a12, a13, b2, b3);
                    }
                }
            }

            // ---- FUSED softmax + PV per 16-token chunk s (tp==s).
            //      wx==3: chunk s feeds only at = s&1. ----
            const int krhA = wy3 ? (((2 * kt)     < 12) ? 1 : 2) : 0;
            const int krhB = wy3 ? (((2 * kt + 1) < 12) ? 1 : 2) : 0;
            #pragma unroll
            for (int s = 0; s < 4; ++s) {
                const bool a0on = !wx3 || ((s & 1) == 0);
                const bool a1on = !wx3 || ((s & 1) == 1);
                unsigned pas[2][4];
                #pragma unroll
                for (int at = 0; at < 2; ++at) {
                    if ((at == 0 && !a0on) || (at == 1 && !a1on)) continue;
                    #pragma unroll
                    for (int tt = 0; tt < 2; ++tt) {
                        const int t = 2 * s + tt;
                        const int krh = (t < 4) ? krhA : krhB;
                        const float bb = (krh == qrh_all) ? 0.f : MASKB;
                        float p0 = ex2f(fmaf(acc[at][t][0], ISL2, bb));
                        float p1 = ex2f(fmaf(acc[at][t][1], ISL2, bb));
                        float p2 = ex2f(fmaf(acc[at][t][2], ISL2, bb));
                        float p3 = ex2f(fmaf(acc[at][t][3], ISL2, bb));
                        lsum[at][0] += p0 + p1;
                        lsum[at][1] += p2 + p3;
                        pas[at][2 * tt]     = h2u(__floats2half2_rn(p0, p1));
                        pas[at][2 * tt + 1] = h2u(__floats2half2_rn(p2, p3));
                    }
                }
                #pragma unroll
                for (int cp = 0; cp < 8; ++cp) {
                    unsigned b0, b1, b2, b3;
                    LDSM_X4_T(b0, b1, b2, b3, v_lds + s * (16 * STRB) + cp * 32);
                    if (a0on) {
                        mma_f16(o[0][2*cp][0], o[0][2*cp][1], o[0][2*cp][2], o[0][2*cp][3],
                                pas[0][0], pas[0][1], pas[0][2], pas[0][3], b0, b1);
                        mma_f16(o[0][2*cp+1][0], o[0][2*cp+1][1], o[0][2*cp+1][2], o[0][2*cp+1][3],
                                pas[0][0], pas[0][1], pas[0][2], pas[0][3], b2, b3);
                    }
                    if (a1on) {
                        mma_f16(o[1][2*cp][0], o[1][2*cp][1], o[1][2*cp][2], o[1][2*cp][3],
                                pas[1][0], pas[1][1], pas[1][2], pas[1][3], b0, b1);
                        mma_f16(o[1][2*cp+1][0], o[1][2*cp+1][1], o[1][2*cp+1][2], o[1][2*cp+1][3],
                                pas[1][0], pas[1][1], pas[1][2], pas[1][3], b2, b3);
                    }
                }
            }
        }
        __syncthreads();
    }

    // ---- finish row sums + epilogue ----
    #pragma unroll
    for (int at = 0; at < 2; ++at) {
        float llo = lsum[at][0], lhi = lsum[at][1];
        llo += __shfl_xor_sync(0xffffffffu, llo, 1);
        llo += __shfl_xor_sync(0xffffffffu, llo, 2);
        lhi += __shfl_xor_sync(0xffffffffu, lhi, 1);
        lhi += __shfl_xor_sync(0xffffffffu, lhi, 2);
        const int tok_lo = qbase + warp * 32 + at * 16 + lr;
        const int gr_lo = grow_idx(b, wy, wx, tok_lo);
        const int gr_hi = grow_idx(b, wy, wx, tok_lo + 8);
        const float ilo = 1.f / llo;
        const float ihi = 1.f / lhi;
        float* out_lo = out + (size_t)gr_lo * C_DIM + 2 * lc;
        float* out_hi = out + (size_t)gr_hi * C_DIM + 2 * lc;
        #pragma unroll
        for (int t = 0; t < 16; ++t) {
            *reinterpret_cast<float2*>(&out_lo[8 * t]) =
                make_float2(o[at][t][0] * ilo, o[at][t][1] * ilo);
            *reinterpret_cast<float2*>(&out_hi[8 * t]) =
                make_float2(o[at][t][2] * ihi, o[at][t][3] * ihi);
        }
    }
}

extern "C" void kernel_launch(void* const* d_in, const int* in_sizes, int n_in,
                              void* d_out, int out_size) {
    (void)in_sizes; (void)n_in; (void)out_size;
    const float* q = (const float*)d_in[0];
    const float* k = (const float*)d_in[1];
    const float* v = (const float*)d_in[2];
    float* out = (float*)d_out;

    prep_f16<<<dim3(NKT, NWIN), 256>>>(k, v);

    cudaFuncSetAttribute(swin_attn_f16,
                         cudaFuncAttributeMaxDynamicSharedMemorySize, SMEM_BYTES);
    swin_attn_f16<<<dim3(NQT, NWIN), 256, SMEM_BYTES>>>(q, out);
}